// round 13
// baseline (speedup 1.0000x reference)
#include <cuda_runtime.h>

#define T25   25
#define HID   100
#define G4    400
#define RT    832             // 26 warps: warps 0-12 = kh0, 13-25 = kh1

typedef unsigned long long u64;

__device__ float g_h1[(size_t)512 * T25 * HID];   // layer1 hidden states

union U4 { float4 f4; ulonglong2 u2; };
union U2 { float2 f2; u64 u; };

__device__ __forceinline__ u64 pk(float lo, float hi) {
    u64 r; asm("mov.b64 %0, {%1,%2};" : "=l"(r) : "f"(lo), "f"(hi)); return r;
}
__device__ __forceinline__ void ffma2(u64& d, u64 a, u64 b) {
    asm("fma.rn.f32x2 %0, %1, %2, %0;" : "+l"(d) : "l"(a), "l"(b));
}
__device__ __forceinline__ float hsum(u64 v) {
    float a, b; asm("mov.b64 {%0,%1}, %2;" : "=f"(a), "=f"(b) : "l"(v)); return a + b;
}
__device__ __forceinline__ float sigm(float x)   { return 1.0f / (1.0f + __expf(-x)); }
__device__ __forceinline__ float mytanh(float x) { float e = __expf(-2.0f * x); return (1.0f - e) / (1.0f + e); }

#define BAR_ARRIVE(id) asm volatile("bar.arrive %0, %1;" :: "r"(id), "r"(RT) : "memory")
#define BAR_SYNCN(id)  asm volatile("bar.sync %0, %1;"   :: "r"(id), "r"(RT) : "memory")

// ---------------- smem layout (floats) ----------------
// [0, 40000)            wz   : W [100][400] during prologue, z [100][400] after
// [40000, 50400)        xs   : x transposed [100][104] (prologue only), reused as:
//   [40000, 40416)      hs   : [4][104]
//   [40416, 43616)      zp2  : float2 [4][400]
//   [43616, 44128)      fc1s : [4][128]
#define OFF_WZ   0
#define OFF_XS   40000
#define OFF_HS   40000
#define OFF_ZP   40416
#define OFF_FC   43616
#define SMEM_FLOATS 50400
#define SMEM_BYTES  (SMEM_FLOATS * 4)   // 201600

// ---------------- prologue GEMM helper ----------------
template<int NQ>
__device__ __forceinline__ void inproj_main(
    const float (*xs)[104], const float* __restrict__ wsm,
    int c, int rb, float bv, U2* accout)
{
    u64 acc[2 * NQ];
    u64 binit = pk(bv, bv);
    #pragma unroll
    for (int p = 0; p < 2 * NQ; p++) acc[p] = binit;

    #pragma unroll 2
    for (int k = 0; k < HID; k++) {
        float w = wsm[k * G4 + c];
        u64 wd = pk(w, w);
        const float* xr = &xs[k][rb];
        #pragma unroll
        for (int q = 0; q < NQ; q++) {
            U4 x; x.f4 = *(const float4*)(xr + 4 * q);
            ffma2(acc[2 * q],     x.u2.x, wd);
            ffma2(acc[2 * q + 1], x.u2.y, wd);
        }
    }
    #pragma unroll
    for (int p = 0; p < 2 * NQ; p++) accout[p].u = acc[p];
}

// ---------------------------------------------------------------------------
// Fused kernel: [stage W + x] -> inproj into smem z -> recurrence -> (h_out | FC)
// 128 blocks x 4 batch rows. GATHER: x = emb[feats] (layer 1) else x = src (h1).
// ---------------------------------------------------------------------------
template<bool GATHER>
__global__ void __launch_bounds__(RT, 1) fused_kernel(
    const int*   __restrict__ feats,  // GATHER: [12800]
    const float* __restrict__ emb,    // GATHER: [VOCAB][100]
    const float* __restrict__ src,    // !GATHER: [12800][100] (h1)
    const float* __restrict__ Wx,     // [100][400] input-projection weights
    const float* __restrict__ bias,   // [400]
    const float* __restrict__ Wh,     // [100][400] recurrent weights
    float*       __restrict__ h_out,  // [12800][100] or null
    const float* __restrict__ wfc1, const float* __restrict__ bfc1,
    const float* __restrict__ wfc2, const float* __restrict__ bfc2,
    float*       __restrict__ out)    // [512][2] or null
{
    extern __shared__ __align__(16) float sm[];
    float* wz = sm + OFF_WZ;                       // W then z
    float (*xs)[104]   = (float(*)[104])(sm + OFF_XS);
    float (*hs)[104]   = (float(*)[104])(sm + OFF_HS);
    float2 (*zp2)[G4]  = (float2(*)[G4])(sm + OFF_ZP);
    float (*fc1s)[128] = (float(*)[128])(sm + OFF_FC);

    const int tid  = threadIdx.x;
    const int b0   = blockIdx.x * 4;
    const int row0 = b0 * T25;                     // global row base (contiguous)

    // ---- stage Wx ----
    for (int i4 = tid; i4 < HID * G4 / 4; i4 += RT)
        ((float4*)wz)[i4] = ((const float4*)Wx)[i4];

    // ---- stage x transposed, batched loads (MLP >= 4) ----
    {
        float4 v[4];
        int    jj[4], rr[4];
        bool   mm[4];
        const float* base[4];
        #pragma unroll
        for (int i = 0; i < 4; i++) {
            int idx = tid + i * RT;
            mm[i] = (idx < 2500);
            jj[i] = idx / 100;
            rr[i] = idx % 100;
        }
        #pragma unroll
        for (int i = 0; i < 4; i++) {
            if (mm[i]) {
                base[i] = GATHER
                    ? emb + (long long)__ldg(feats + row0 + rr[i]) * HID
                    : src + (long long)(row0 + rr[i]) * HID;
            }
        }
        #pragma unroll
        for (int i = 0; i < 4; i++)
            if (mm[i]) v[i] = *(const float4*)(base[i] + 4 * jj[i]);
        #pragma unroll
        for (int i = 0; i < 4; i++) {
            if (mm[i]) {
                xs[4 * jj[i] + 0][rr[i]] = v[i].x;
                xs[4 * jj[i] + 1][rr[i]] = v[i].y;
                xs[4 * jj[i] + 2][rr[i]] = v[i].z;
                xs[4 * jj[i] + 3][rr[i]] = v[i].w;
            }
        }
    }
    __syncthreads();

    // ---- prologue GEMM: z[rl][c] = bias[c] + x[rl]@Wx[:,c]  (tid < 800) ----
    U2 zacc[26];
    int zrb = 0, znq = 0;
    if (tid < 800) {
        const int c  = tid % G4;
        const int rg = tid / G4;
        const float bv = __ldg(bias + c);
        if (rg == 0) { zrb = 0;  znq = 13; inproj_main<13>(xs, wz, c, 0,  bv, zacc); }
        else         { zrb = 52; znq = 12; inproj_main<12>(xs, wz, c, 52, bv, zacc); }
    }
    __syncthreads();                  // all W reads complete before overwrite

    // ---- store z over W; init hs; load recurrent weights ----
    if (tid < 800) {
        const int c = tid % G4;
        for (int p = 0; p < znq * 2; p++) {
            wz[(zrb + 2 * p    ) * G4 + c] = zacc[p].f2.x;
            wz[(zrb + 2 * p + 1) * G4 + c] = zacc[p].f2.y;
        }
    }
    for (int i = tid; i < 4 * 104; i += RT) ((float*)hs)[i] = 0.f;

    const int wid = tid >> 5;
    const int kh  = (wid >= 13);
    const int c   = tid - (kh ? 416 : 0);           // 0..415
    const bool act = (c < G4);
    const int gr = c / 100;
    const int gu = c % 100;

    u64 wp[26];
    #pragma unroll
    for (int j = 0; j < 26; j++) {
        int k = kh * 52 + 2 * j;
        float w0 = (act && k     < HID) ? __ldg(Wh + (k    ) * G4 + c) : 0.f;
        float w1 = (act && k + 1 < HID) ? __ldg(Wh + (k + 1) * G4 + c) : 0.f;
        wp[j] = pk(w0, w1);
    }
    __syncthreads();

    // ---- recurrence: 25 steps, split barriers, z read from smem ----
    float cst = 0.f;
    for (int t = 0; t < T25; t++) {
        if (act) {
            u64 a0 = 0ULL, a1 = 0ULL, a2 = 0ULL, a3 = 0ULL;
            if (kh == 0) {
                #pragma unroll
                for (int j4 = 0; j4 < 13; j4++) {
                    U4 v0; v0.f4 = *(const float4*)&hs[0][4 * j4];
                    U4 v1; v1.f4 = *(const float4*)&hs[1][4 * j4];
                    U4 v2; v2.f4 = *(const float4*)&hs[2][4 * j4];
                    U4 v3; v3.f4 = *(const float4*)&hs[3][4 * j4];
                    ffma2(a0, v0.u2.x, wp[2 * j4]); ffma2(a0, v0.u2.y, wp[2 * j4 + 1]);
                    ffma2(a1, v1.u2.x, wp[2 * j4]); ffma2(a1, v1.u2.y, wp[2 * j4 + 1]);
                    ffma2(a2, v2.u2.x, wp[2 * j4]); ffma2(a2, v2.u2.y, wp[2 * j4 + 1]);
                    ffma2(a3, v3.u2.x, wp[2 * j4]); ffma2(a3, v3.u2.y, wp[2 * j4 + 1]);
                }
            } else {
                #pragma unroll
                for (int j4 = 0; j4 < 12; j4++) {
                    U4 v0; v0.f4 = *(const float4*)&hs[0][52 + 4 * j4];
                    U4 v1; v1.f4 = *(const float4*)&hs[1][52 + 4 * j4];
                    U4 v2; v2.f4 = *(const float4*)&hs[2][52 + 4 * j4];
                    U4 v3; v3.f4 = *(const float4*)&hs[3][52 + 4 * j4];
                    ffma2(a0, v0.u2.x, wp[2 * j4]); ffma2(a0, v0.u2.y, wp[2 * j4 + 1]);
                    ffma2(a1, v1.u2.x, wp[2 * j4]); ffma2(a1, v1.u2.y, wp[2 * j4 + 1]);
                    ffma2(a2, v2.u2.x, wp[2 * j4]); ffma2(a2, v2.u2.y, wp[2 * j4 + 1]);
                    ffma2(a3, v3.u2.x, wp[2 * j4]); ffma2(a3, v3.u2.y, wp[2 * j4 + 1]);
                }
            }
            float* zpf = (float*)&zp2[0][0] + 2 * c + kh;
            zpf[0 * G4 * 2] = hsum(a0);
            zpf[1 * G4 * 2] = hsum(a1);
            zpf[2 * G4 * 2] = hsum(a2);
            zpf[3 * G4 * 2] = hsum(a3);
        }

        if (kh) {
            BAR_ARRIVE(1);
            BAR_SYNCN(2);
        } else {
            BAR_SYNCN(1);
            if (act) {
                const float* zrow = wz + (gr * T25 + t) * G4;
                float2 p0 = zp2[gr][gu];
                float2 p1 = zp2[gr][gu + 100];
                float2 p2 = zp2[gr][gu + 200];
                float2 p3 = zp2[gr][gu + 300];
                float zi = zrow[gu]       + p0.x + p0.y;
                float zj = zrow[gu + 100] + p1.x + p1.y;
                float zf = zrow[gu + 200] + p2.x + p2.y;
                float zo = zrow[gu + 300] + p3.x + p3.y;
                cst = cst * sigm(zf + 1.0f) + sigm(zi) * mytanh(zj);
                float hn = mytanh(cst) * sigm(zo);
                hs[gr][gu] = hn;
                if (h_out)
                    h_out[((long long)(b0 + gr) * T25 + t) * HID + gu] = hn;
            }
            BAR_SYNCN(2);
        }
    }

    // ---- FC head (layer-2 kernel only) ----
    if (out) {
        __syncthreads();
        for (int idx = tid; idx < 4 * 128; idx += RT) {
            int r = idx / 128, j = idx % 128;
            float a = bfc1[j];
            #pragma unroll 4
            for (int k = 0; k < HID; k++)
                a += hs[r][k] * __ldg(wfc1 + k * 128 + j);
            fc1s[r][j] = a;
        }
        __syncthreads();
        if (tid < 8) {
            int r = tid / 2, cc = tid % 2;
            float a = bfc2[cc];
            #pragma unroll 8
            for (int k = 0; k < 128; k++)
                a += fc1s[r][k] * __ldg(wfc2 + k * 2 + cc);
            out[(b0 + r) * 2 + cc] = a;
        }
    }
}

// ---------------------------------------------------------------------------
extern "C" void kernel_launch(void* const* d_in, const int* in_sizes, int n_in,
                              void* d_out, int out_size)
{
    const int*   feats = (const int*)  d_in[0];
    const float* emb   = (const float*)d_in[1];
    const float* k1    = (const float*)d_in[2];
    const float* b1    = (const float*)d_in[3];
    const float* k2    = (const float*)d_in[4];
    const float* b2    = (const float*)d_in[5];
    const float* wfc1  = (const float*)d_in[6];
    const float* bfc1  = (const float*)d_in[7];
    const float* wfc2  = (const float*)d_in[8];
    const float* bfc2  = (const float*)d_in[9];
    float* out = (float*)d_out;

    float* h1 = nullptr;
    cudaGetSymbolAddress((void**)&h1, g_h1);

    cudaFuncSetAttribute(fused_kernel<true>,
                         cudaFuncAttributeMaxDynamicSharedMemorySize, SMEM_BYTES);
    cudaFuncSetAttribute(fused_kernel<false>,
                         cudaFuncAttributeMaxDynamicSharedMemorySize, SMEM_BYTES);

    // Layer 1: gather + inproj + recurrence -> h1
    fused_kernel<true><<<128, RT, SMEM_BYTES>>>(
        feats, emb, nullptr, k1, b1, k1 + HID * G4, h1,
        nullptr, nullptr, nullptr, nullptr, nullptr);
    // Layer 2: inproj(h1) + recurrence + FC head -> out
    fused_kernel<false><<<128, RT, SMEM_BYTES>>>(
        nullptr, nullptr, h1, k2, b2, k2 + HID * G4, nullptr,
        wfc1, bfc1, wfc2, bfc2, out);
}

// round 14
// speedup vs baseline: 1.0823x; 1.0823x over previous
#include <cuda_runtime.h>

#define T25   25
#define HID   100
#define G4    400
#define RT    832             // 26 warps: warps 0-12 = kh0, 13-25 = kh1

typedef unsigned long long u64;

__device__ float g_h1[(size_t)512 * T25 * HID];   // layer1 hidden states

union U4 { float4 f4; ulonglong2 u2; };
union U2 { float2 f2; u64 u; };

__device__ __forceinline__ u64 pk(float lo, float hi) {
    u64 r; asm("mov.b64 %0, {%1,%2};" : "=l"(r) : "f"(lo), "f"(hi)); return r;
}
__device__ __forceinline__ void ffma2(u64& d, u64 a, u64 b) {
    asm("fma.rn.f32x2 %0, %1, %2, %0;" : "+l"(d) : "l"(a), "l"(b));
}
__device__ __forceinline__ float hsum(u64 v) {
    float a, b; asm("mov.b64 {%0,%1}, %2;" : "=f"(a), "=f"(b) : "l"(v)); return a + b;
}
__device__ __forceinline__ float sigm(float x)   { return 1.0f / (1.0f + __expf(-x)); }
__device__ __forceinline__ float mytanh(float x) { float e = __expf(-2.0f * x); return (1.0f - e) / (1.0f + e); }

#define BAR_ARRIVE(id) asm volatile("bar.arrive %0, %1;" :: "r"(id), "r"(RT) : "memory")
#define BAR_SYNCN(id)  asm volatile("bar.sync %0, %1;"   :: "r"(id), "r"(RT) : "memory")

// ---------------- smem layout (floats) ----------------
#define OFF_WZ   0            // W [100][400] during prologue, z [100][400] after
#define OFF_XS   40000        // x transposed [100][104] (prologue), reused as:
#define OFF_HS   40000        //   hs [4][104]
#define OFF_ZP   40416        //   zp2 float2 [4][400]
#define OFF_FC   43616        //   fc1s [4][128]
#define SMEM_FLOATS 50400
#define SMEM_BYTES  (SMEM_FLOATS * 4)   // 201600

// ---------------- prologue GEMM helper (compute only, compile-time NQ) -----
template<int NQ>
__device__ __forceinline__ void inproj_compute(
    const float (*xs)[104], const float* __restrict__ wsm,
    int c, int rb, float bv, u64* acc)
{
    u64 binit = pk(bv, bv);
    #pragma unroll
    for (int p = 0; p < 2 * NQ; p++) acc[p] = binit;

    #pragma unroll 2
    for (int k = 0; k < HID; k++) {
        float w = wsm[k * G4 + c];
        u64 wd = pk(w, w);
        const float* xr = &xs[k][rb];
        #pragma unroll
        for (int q = 0; q < NQ; q++) {
            U4 x; x.f4 = *(const float4*)(xr + 4 * q);
            ffma2(acc[2 * q],     x.u2.x, wd);
            ffma2(acc[2 * q + 1], x.u2.y, wd);
        }
    }
}

// compile-time-bounded store: zacc stays in registers
template<int NQ>
__device__ __forceinline__ void inproj_store(
    float* __restrict__ wz, const u64* acc, int c, int rb)
{
    float* p0 = wz + rb * G4 + c;
    #pragma unroll
    for (int p = 0; p < 2 * NQ; p++) {
        U2 v; v.u = acc[p];
        p0[(2 * p    ) * G4] = v.f2.x;
        p0[(2 * p + 1) * G4] = v.f2.y;
    }
}

// ---------------------------------------------------------------------------
// Fused kernel: [stage W + x] -> inproj into smem z -> recurrence -> (h_out|FC)
// ---------------------------------------------------------------------------
template<bool GATHER>
__global__ void __launch_bounds__(RT, 1) fused_kernel(
    const int*   __restrict__ feats,
    const float* __restrict__ emb,
    const float* __restrict__ src,
    const float* __restrict__ Wx,     // [100][400]
    const float* __restrict__ bias,   // [400]
    const float* __restrict__ Wh,     // [100][400]
    float*       __restrict__ h_out,  // [12800][100] or null
    const float* __restrict__ wfc1, const float* __restrict__ bfc1,
    const float* __restrict__ wfc2, const float* __restrict__ bfc2,
    float*       __restrict__ out)    // [512][2] or null
{
    extern __shared__ __align__(16) float sm[];
    float* wz = sm + OFF_WZ;
    float (*xs)[104]   = (float(*)[104])(sm + OFF_XS);
    float (*hs)[104]   = (float(*)[104])(sm + OFF_HS);
    float2 (*zp2)[G4]  = (float2(*)[G4])(sm + OFF_ZP);
    float (*fc1s)[128] = (float(*)[128])(sm + OFF_FC);

    const int tid  = threadIdx.x;
    const int b0   = blockIdx.x * 4;
    const int row0 = b0 * T25;

    // ---- stage Wx ----
    for (int i4 = tid; i4 < HID * G4 / 4; i4 += RT)
        ((float4*)wz)[i4] = ((const float4*)Wx)[i4];

    // ---- stage x transposed, batched loads (MLP >= 4) ----
    {
        float4 v[4];
        int    jj[4], rr[4];
        bool   mm[4];
        const float* base[4];
        #pragma unroll
        for (int i = 0; i < 4; i++) {
            int idx = tid + i * RT;
            mm[i] = (idx < 2500);
            jj[i] = idx / 100;
            rr[i] = idx % 100;
        }
        #pragma unroll
        for (int i = 0; i < 4; i++) {
            if (mm[i]) {
                base[i] = GATHER
                    ? emb + (long long)__ldg(feats + row0 + rr[i]) * HID
                    : src + (long long)(row0 + rr[i]) * HID;
            }
        }
        #pragma unroll
        for (int i = 0; i < 4; i++)
            if (mm[i]) v[i] = *(const float4*)(base[i] + 4 * jj[i]);
        #pragma unroll
        for (int i = 0; i < 4; i++) {
            if (mm[i]) {
                xs[4 * jj[i] + 0][rr[i]] = v[i].x;
                xs[4 * jj[i] + 1][rr[i]] = v[i].y;
                xs[4 * jj[i] + 2][rr[i]] = v[i].z;
                xs[4 * jj[i] + 3][rr[i]] = v[i].w;
            }
        }
    }
    __syncthreads();

    // ---- prologue GEMM (compute into registers, compile-time bounds) ----
    u64 zacc[26];
    const int pc = tid % G4;      // prologue column
    const int rg = tid / G4;      // 0,1 valid; 2 (tid>=800) idle
    if (rg == 0)      inproj_compute<13>(xs, wz, pc, 0,  __ldg(bias + pc), zacc);
    else if (rg == 1) inproj_compute<12>(xs, wz, pc, 52, __ldg(bias + pc), zacc);
    __syncthreads();              // all W reads complete before overwrite

    // ---- store z over W (compile-time unrolled; zacc in registers) ----
    if (rg == 0)      inproj_store<13>(wz, zacc, pc, 0);
    else if (rg == 1) inproj_store<12>(wz, zacc, pc, 52);
    for (int i = tid; i < 4 * 104; i += RT) ((float*)hs)[i] = 0.f;

    const int wid = tid >> 5;
    const int kh  = (wid >= 13);
    const int c   = tid - (kh ? 416 : 0);           // 0..415
    const bool act = (c < G4);
    const int gr = c / 100;
    const int gu = c % 100;

    u64 wp[26];
    #pragma unroll
    for (int j = 0; j < 26; j++) {
        int k = kh * 52 + 2 * j;
        float w0 = (act && k     < HID) ? __ldg(Wh + (k    ) * G4 + c) : 0.f;
        float w1 = (act && k + 1 < HID) ? __ldg(Wh + (k + 1) * G4 + c) : 0.f;
        wp[j] = pk(w0, w1);
    }
    __syncthreads();

    // ---- recurrence: 25 steps, split barriers, z read from smem ----
    float cst = 0.f;
    for (int t = 0; t < T25; t++) {
        if (act) {
            u64 a0 = 0ULL, a1 = 0ULL, a2 = 0ULL, a3 = 0ULL;
            if (kh == 0) {
                #pragma unroll
                for (int j4 = 0; j4 < 13; j4++) {
                    U4 v0; v0.f4 = *(const float4*)&hs[0][4 * j4];
                    U4 v1; v1.f4 = *(const float4*)&hs[1][4 * j4];
                    U4 v2; v2.f4 = *(const float4*)&hs[2][4 * j4];
                    U4 v3; v3.f4 = *(const float4*)&hs[3][4 * j4];
                    ffma2(a0, v0.u2.x, wp[2 * j4]); ffma2(a0, v0.u2.y, wp[2 * j4 + 1]);
                    ffma2(a1, v1.u2.x, wp[2 * j4]); ffma2(a1, v1.u2.y, wp[2 * j4 + 1]);
                    ffma2(a2, v2.u2.x, wp[2 * j4]); ffma2(a2, v2.u2.y, wp[2 * j4 + 1]);
                    ffma2(a3, v3.u2.x, wp[2 * j4]); ffma2(a3, v3.u2.y, wp[2 * j4 + 1]);
                }
            } else {
                #pragma unroll
                for (int j4 = 0; j4 < 12; j4++) {
                    U4 v0; v0.f4 = *(const float4*)&hs[0][52 + 4 * j4];
                    U4 v1; v1.f4 = *(const float4*)&hs[1][52 + 4 * j4];
                    U4 v2; v2.f4 = *(const float4*)&hs[2][52 + 4 * j4];
                    U4 v3; v3.f4 = *(const float4*)&hs[3][52 + 4 * j4];
                    ffma2(a0, v0.u2.x, wp[2 * j4]); ffma2(a0, v0.u2.y, wp[2 * j4 + 1]);
                    ffma2(a1, v1.u2.x, wp[2 * j4]); ffma2(a1, v1.u2.y, wp[2 * j4 + 1]);
                    ffma2(a2, v2.u2.x, wp[2 * j4]); ffma2(a2, v2.u2.y, wp[2 * j4 + 1]);
                    ffma2(a3, v3.u2.x, wp[2 * j4]); ffma2(a3, v3.u2.y, wp[2 * j4 + 1]);
                }
            }
            float* zpf = (float*)&zp2[0][0] + 2 * c + kh;
            zpf[0 * G4 * 2] = hsum(a0);
            zpf[1 * G4 * 2] = hsum(a1);
            zpf[2 * G4 * 2] = hsum(a2);
            zpf[3 * G4 * 2] = hsum(a3);
        }

        if (kh) {
            BAR_ARRIVE(1);
            BAR_SYNCN(2);
        } else {
            BAR_SYNCN(1);
            if (act) {
                const float* zrow = wz + (gr * T25 + t) * G4;
                float2 p0 = zp2[gr][gu];
                float2 p1 = zp2[gr][gu + 100];
                float2 p2 = zp2[gr][gu + 200];
                float2 p3 = zp2[gr][gu + 300];
                float zi = zrow[gu]       + p0.x + p0.y;
                float zj = zrow[gu + 100] + p1.x + p1.y;
                float zf = zrow[gu + 200] + p2.x + p2.y;
                float zo = zrow[gu + 300] + p3.x + p3.y;
                cst = cst * sigm(zf + 1.0f) + sigm(zi) * mytanh(zj);
                float hn = mytanh(cst) * sigm(zo);
                hs[gr][gu] = hn;
                if (h_out)
                    h_out[((long long)(b0 + gr) * T25 + t) * HID + gu] = hn;
            }
            BAR_SYNCN(2);
        }
    }

    // ---- FC head (layer-2 kernel only) ----
    if (out) {
        __syncthreads();
        for (int idx = tid; idx < 4 * 128; idx += RT) {
            int r = idx / 128, j = idx % 128;
            float a = bfc1[j];
            #pragma unroll 4
            for (int k = 0; k < HID; k++)
                a += hs[r][k] * __ldg(wfc1 + k * 128 + j);
            fc1s[r][j] = a;
        }
        __syncthreads();
        if (tid < 8) {
            int r = tid / 2, cc = tid % 2;
            float a = bfc2[cc];
            #pragma unroll 8
            for (int k = 0; k < 128; k++)
                a += fc1s[r][k] * __ldg(wfc2 + k * 2 + cc);
            out[(b0 + r) * 2 + cc] = a;
        }
    }
}

// ---------------------------------------------------------------------------
extern "C" void kernel_launch(void* const* d_in, const int* in_sizes, int n_in,
                              void* d_out, int out_size)
{
    const int*   feats = (const int*)  d_in[0];
    const float* emb   = (const float*)d_in[1];
    const float* k1    = (const float*)d_in[2];
    const float* b1    = (const float*)d_in[3];
    const float* k2    = (const float*)d_in[4];
    const float* b2    = (const float*)d_in[5];
    const float* wfc1  = (const float*)d_in[6];
    const float* bfc1  = (const float*)d_in[7];
    const float* wfc2  = (const float*)d_in[8];
    const float* bfc2  = (const float*)d_in[9];
    float* out = (float*)d_out;

    float* h1 = nullptr;
    cudaGetSymbolAddress((void**)&h1, g_h1);

    cudaFuncSetAttribute(fused_kernel<true>,
                         cudaFuncAttributeMaxDynamicSharedMemorySize, SMEM_BYTES);
    cudaFuncSetAttribute(fused_kernel<false>,
                         cudaFuncAttributeMaxDynamicSharedMemorySize, SMEM_BYTES);

    // Layer 1: gather + inproj + recurrence -> h1
    fused_kernel<true><<<128, RT, SMEM_BYTES>>>(
        feats, emb, nullptr, k1, b1, k1 + HID * G4, h1,
        nullptr, nullptr, nullptr, nullptr, nullptr);
    // Layer 2: inproj(h1) + recurrence + FC head -> out
    fused_kernel<false><<<128, RT, SMEM_BYTES>>>(
        nullptr, nullptr, h1, k2, b2, k2 + HID * G4, nullptr,
        wfc1, bfc1, wfc2, bfc2, out);
}

// round 15
// speedup vs baseline: 1.1039x; 1.0200x over previous
#include <cuda_runtime.h>

#define T25   25
#define HID   100
#define G4    400
#define RT    832             // 26 warps: warps 0-12 = kh0, 13-25 = kh1

typedef unsigned long long u64;

__device__ float g_z2x[(size_t)512 * T25 * G4];   // layer2 input projection

union U4 { float4 f4; ulonglong2 u2; };
union U2 { float2 f2; u64 u; };

__device__ __forceinline__ u64 pk(float lo, float hi) {
    u64 r; asm("mov.b64 %0, {%1,%2};" : "=l"(r) : "f"(lo), "f"(hi)); return r;
}
__device__ __forceinline__ void ffma2(u64& d, u64 a, u64 b) {
    asm("fma.rn.f32x2 %0, %1, %2, %0;" : "+l"(d) : "l"(a), "l"(b));
}
__device__ __forceinline__ float hsum(u64 v) {
    float a, b; asm("mov.b64 {%0,%1}, %2;" : "=f"(a), "=f"(b) : "l"(v)); return a + b;
}
__device__ __forceinline__ float sigm(float x)   { return 1.0f / (1.0f + __expf(-x)); }
__device__ __forceinline__ float mytanh(float x) { float e = __expf(-2.0f * x); return (1.0f - e) / (1.0f + e); }

#define BAR_ARRIVE(id) asm volatile("bar.arrive %0, %1;" :: "r"(id), "r"(RT) : "memory")
#define BAR_SYNCN(id)  asm volatile("bar.sync %0, %1;"   :: "r"(id), "r"(RT) : "memory")

// ---------------- kernel1 smem layout (floats) ----------------
// [0, 40000)       wz  : k1x during prologue -> z1 during rec -> k2x -> (z2 in regs)
// [40000, 40416)   hs  : [4][104]
// [40416, 43616)   zp2 : float2 [4][400]
// [43616, 54016)   xh  : x transposed [100][104] (prologue) -> h1s [100][104] (rec+tail)
#define OFF_WZ   0
#define OFF_HS   40000
#define OFF_ZP   40416
#define OFF_XH   43616
#define K1_SMEM_FLOATS 54016
#define K1_SMEM_BYTES  (K1_SMEM_FLOATS * 4)   // 216064

// ---------------- prologue GEMM helpers (compile-time bounds, spill-free) --
template<int NQ>
__device__ __forceinline__ void inproj_compute(
    const float (*xs)[104], const float* __restrict__ wsm,
    int c, int rb, float bv, u64* acc)
{
    u64 binit = pk(bv, bv);
    #pragma unroll
    for (int p = 0; p < 2 * NQ; p++) acc[p] = binit;

    #pragma unroll 2
    for (int k = 0; k < HID; k++) {
        float w = wsm[k * G4 + c];
        u64 wd = pk(w, w);
        const float* xr = &xs[k][rb];
        #pragma unroll
        for (int q = 0; q < NQ; q++) {
            U4 x; x.f4 = *(const float4*)(xr + 4 * q);
            ffma2(acc[2 * q],     x.u2.x, wd);
            ffma2(acc[2 * q + 1], x.u2.y, wd);
        }
    }
}

template<int NQ>
__device__ __forceinline__ void store_smem(
    float* __restrict__ dst, const u64* acc, int c, int rb)
{
    float* p0 = dst + rb * G4 + c;
    #pragma unroll
    for (int p = 0; p < 2 * NQ; p++) {
        U2 v; v.u = acc[p];
        p0[(2 * p    ) * G4] = v.f2.x;
        p0[(2 * p + 1) * G4] = v.f2.y;
    }
}

template<int NQ>
__device__ __forceinline__ void store_gmem(
    float* __restrict__ dst, const u64* acc, int c, int rb, int row0)
{
    float* p0 = dst + (long long)(row0 + rb) * G4 + c;
    #pragma unroll
    for (int p = 0; p < 2 * NQ; p++) {
        U2 v; v.u = acc[p];
        p0[(long long)(2 * p    ) * G4] = v.f2.x;
        p0[(long long)(2 * p + 1) * G4] = v.f2.y;
    }
}

// ---------------------------------------------------------------------------
// Kernel 1 (A+B+C): emb gather -> inproj1 (smem z1) -> rec layer1 (h1 in smem)
//                   -> stage k2x -> z2 = h1 @ k2x + b2 -> global g_z2x
// 128 blocks x 4 batch rows.
// ---------------------------------------------------------------------------
__global__ void __launch_bounds__(RT, 1) abc_kernel(
    const int*   __restrict__ feats,  // [12800]
    const float* __restrict__ emb,    // [VOCAB][100]
    const float* __restrict__ k1,     // [200][400]
    const float* __restrict__ b1,     // [400]
    const float* __restrict__ k2,     // [200][400]
    const float* __restrict__ b2,     // [400]
    float*       __restrict__ z2out)  // [12800][400]
{
    extern __shared__ __align__(16) float sm[];
    float* wz = sm + OFF_WZ;
    float (*hs)[104]   = (float(*)[104])(sm + OFF_HS);
    float2 (*zp2)[G4]  = (float2(*)[G4])(sm + OFF_ZP);
    float (*xh)[104]   = (float(*)[104])(sm + OFF_XH);   // xs then h1s

    const int tid  = threadIdx.x;
    const int row0 = blockIdx.x * 100;    // global z-row base (= b0*25)

    // ---- phase 1: stage k1x + gather x transposed (MLP-batched) ----
    for (int i4 = tid; i4 < HID * G4 / 4; i4 += RT)
        ((float4*)wz)[i4] = ((const float4*)k1)[i4];
    {
        float4 v[4];
        int    jj[4], rr[4];
        bool   mm[4];
        const float* base[4];
        #pragma unroll
        for (int i = 0; i < 4; i++) {
            int idx = tid + i * RT;
            mm[i] = (idx < 2500);
            jj[i] = idx / 100;
            rr[i] = idx % 100;
        }
        #pragma unroll
        for (int i = 0; i < 4; i++)
            if (mm[i]) base[i] = emb + (long long)__ldg(feats + row0 + rr[i]) * HID;
        #pragma unroll
        for (int i = 0; i < 4; i++)
            if (mm[i]) v[i] = *(const float4*)(base[i] + 4 * jj[i]);
        #pragma unroll
        for (int i = 0; i < 4; i++) {
            if (mm[i]) {
                xh[4 * jj[i] + 0][rr[i]] = v[i].x;
                xh[4 * jj[i] + 1][rr[i]] = v[i].y;
                xh[4 * jj[i] + 2][rr[i]] = v[i].z;
                xh[4 * jj[i] + 3][rr[i]] = v[i].w;
            }
        }
    }
    __syncthreads();

    // ---- phase 2: prologue GEMM z1 = x @ k1x + b1 (registers) ----
    u64 zacc[26];
    const int pc = tid % G4;
    const int rg = tid / G4;              // 0,1 compute; 2 idle
    if (rg == 0)      inproj_compute<13>(xh, wz, pc, 0,  __ldg(b1 + pc), zacc);
    else if (rg == 1) inproj_compute<12>(xh, wz, pc, 52, __ldg(b1 + pc), zacc);
    __syncthreads();                      // all k1x reads done

    // ---- phase 3: z1 over wz; init hs; load recurrent weights k1h ----
    if (rg == 0)      store_smem<13>(wz, zacc, pc, 0);
    else if (rg == 1) store_smem<12>(wz, zacc, pc, 52);
    for (int i = tid; i < 4 * 104; i += RT) ((float*)hs)[i] = 0.f;

    const int wid = tid >> 5;
    const int kh  = (wid >= 13);
    const int c   = tid - (kh ? 416 : 0);
    const bool act = (c < G4);
    const int gr = c / 100;
    const int gu = c % 100;

    const float* Wh = k1 + HID * G4;
    u64 wp[26];
    #pragma unroll
    for (int j = 0; j < 26; j++) {
        int k = kh * 52 + 2 * j;
        float w0 = (act && k     < HID) ? __ldg(Wh + (k    ) * G4 + c) : 0.f;
        float w1 = (act && k + 1 < HID) ? __ldg(Wh + (k + 1) * G4 + c) : 0.f;
        wp[j] = pk(w0, w1);
    }
    __syncthreads();

    // ---- phase 4: recurrence, h1 kept in smem (xh region) ----
    float cst = 0.f;
    for (int t = 0; t < T25; t++) {
        if (act) {
            u64 a0 = 0ULL, a1 = 0ULL, a2 = 0ULL, a3 = 0ULL;
            if (kh == 0) {
                #pragma unroll
                for (int j4 = 0; j4 < 13; j4++) {
                    U4 v0; v0.f4 = *(const float4*)&hs[0][4 * j4];
                    U4 v1; v1.f4 = *(const float4*)&hs[1][4 * j4];
                    U4 v2; v2.f4 = *(const float4*)&hs[2][4 * j4];
                    U4 v3; v3.f4 = *(const float4*)&hs[3][4 * j4];
                    ffma2(a0, v0.u2.x, wp[2 * j4]); ffma2(a0, v0.u2.y, wp[2 * j4 + 1]);
                    ffma2(a1, v1.u2.x, wp[2 * j4]); ffma2(a1, v1.u2.y, wp[2 * j4 + 1]);
                    ffma2(a2, v2.u2.x, wp[2 * j4]); ffma2(a2, v2.u2.y, wp[2 * j4 + 1]);
                    ffma2(a3, v3.u2.x, wp[2 * j4]); ffma2(a3, v3.u2.y, wp[2 * j4 + 1]);
                }
            } else {
                #pragma unroll
                for (int j4 = 0; j4 < 12; j4++) {
                    U4 v0; v0.f4 = *(const float4*)&hs[0][52 + 4 * j4];
                    U4 v1; v1.f4 = *(const float4*)&hs[1][52 + 4 * j4];
                    U4 v2; v2.f4 = *(const float4*)&hs[2][52 + 4 * j4];
                    U4 v3; v3.f4 = *(const float4*)&hs[3][52 + 4 * j4];
                    ffma2(a0, v0.u2.x, wp[2 * j4]); ffma2(a0, v0.u2.y, wp[2 * j4 + 1]);
                    ffma2(a1, v1.u2.x, wp[2 * j4]); ffma2(a1, v1.u2.y, wp[2 * j4 + 1]);
                    ffma2(a2, v2.u2.x, wp[2 * j4]); ffma2(a2, v2.u2.y, wp[2 * j4 + 1]);
                    ffma2(a3, v3.u2.x, wp[2 * j4]); ffma2(a3, v3.u2.y, wp[2 * j4 + 1]);
                }
            }
            float* zpf = (float*)&zp2[0][0] + 2 * c + kh;
            zpf[0 * G4 * 2] = hsum(a0);
            zpf[1 * G4 * 2] = hsum(a1);
            zpf[2 * G4 * 2] = hsum(a2);
            zpf[3 * G4 * 2] = hsum(a3);
        }

        if (kh) {
            BAR_ARRIVE(1);
            BAR_SYNCN(2);
        } else {
            BAR_SYNCN(1);
            if (act) {
                const float* zrow = wz + (gr * T25 + t) * G4;
                float2 p0 = zp2[gr][gu];
                float2 p1 = zp2[gr][gu + 100];
                float2 p2 = zp2[gr][gu + 200];
                float2 p3 = zp2[gr][gu + 300];
                float zi = zrow[gu]       + p0.x + p0.y;
                float zj = zrow[gu + 100] + p1.x + p1.y;
                float zf = zrow[gu + 200] + p2.x + p2.y;
                float zo = zrow[gu + 300] + p3.x + p3.y;
                cst = cst * sigm(zf + 1.0f) + sigm(zi) * mytanh(zj);
                float hn = mytanh(cst) * sigm(zo);
                hs[gr][gu] = hn;
                xh[gu][gr * T25 + t] = hn;     // h1s[k][row], transposed for C
            }
            BAR_SYNCN(2);
        }
    }
    __syncthreads();

    // ---- phase 5: stage k2x over consumed z1 ----
    for (int i4 = tid; i4 < HID * G4 / 4; i4 += RT)
        ((float4*)wz)[i4] = ((const float4*)k2)[i4];
    __syncthreads();

    // ---- phase 6: z2 = h1 @ k2x + b2 -> global ----
    if (rg == 0) {
        inproj_compute<13>(xh, wz, pc, 0,  __ldg(b2 + pc), zacc);
        store_gmem<13>(z2out, zacc, pc, 0, row0);
    } else if (rg == 1) {
        inproj_compute<12>(xh, wz, pc, 52, __ldg(b2 + pc), zacc);
        store_gmem<12>(z2out, zacc, pc, 52, row0);
    }
}

// ---------------------------------------------------------------------------
// Kernel 2 (D): layer-2 recurrence (R12 proven config) + FC head.
// ---------------------------------------------------------------------------
__global__ void __launch_bounds__(RT, 1) rec2_kernel(
    const float* __restrict__ zin,    // [12800][400] = g_z2x
    const float* __restrict__ Wh,     // k2[100:200][400]
    const float* __restrict__ wfc1, const float* __restrict__ bfc1,
    const float* __restrict__ wfc2, const float* __restrict__ bfc2,
    float*       __restrict__ out)    // [512][2]
{
    __shared__ __align__(16) float  hs[4][104];
    __shared__ __align__(16) float2 zp2[4][G4];
    __shared__ float zsm[2][4][G4];
    __shared__ float fc1s[4][128];

    const int tid = threadIdx.x;
    const int b0  = blockIdx.x * 4;
    const int wid = tid >> 5;
    const int kh  = (wid >= 13);
    const int c   = tid - (kh ? 416 : 0);
    const bool act = (c < G4);
    const int gr = c / 100;
    const int gu = c % 100;

    u64 wp[26];
    #pragma unroll
    for (int j = 0; j < 26; j++) {
        int k = kh * 52 + 2 * j;
        float w0 = (act && k     < HID) ? __ldg(Wh + (k    ) * G4 + c) : 0.f;
        float w1 = (act && k + 1 < HID) ? __ldg(Wh + (k + 1) * G4 + c) : 0.f;
        wp[j] = pk(w0, w1);
    }
    for (int i = tid; i < 4 * 104; i += RT) ((float*)hs)[i] = 0.f;

    if (kh && act) {
        const float* zr = zin + ((long long)(b0 + gr) * T25 + 0) * G4 + gu;
        zsm[0][0][c] = __ldg(zr);
        zsm[0][1][c] = __ldg(zr + 100);
        zsm[0][2][c] = __ldg(zr + 200);
        zsm[0][3][c] = __ldg(zr + 300);
    }
    __syncthreads();

    float cst = 0.f;
    for (int t = 0; t < T25; t++) {
        if (act) {
            u64 a0 = 0ULL, a1 = 0ULL, a2 = 0ULL, a3 = 0ULL;
            if (kh == 0) {
                #pragma unroll
                for (int j4 = 0; j4 < 13; j4++) {
                    U4 v0; v0.f4 = *(const float4*)&hs[0][4 * j4];
                    U4 v1; v1.f4 = *(const float4*)&hs[1][4 * j4];
                    U4 v2; v2.f4 = *(const float4*)&hs[2][4 * j4];
                    U4 v3; v3.f4 = *(const float4*)&hs[3][4 * j4];
                    ffma2(a0, v0.u2.x, wp[2 * j4]); ffma2(a0, v0.u2.y, wp[2 * j4 + 1]);
                    ffma2(a1, v1.u2.x, wp[2 * j4]); ffma2(a1, v1.u2.y, wp[2 * j4 + 1]);
                    ffma2(a2, v2.u2.x, wp[2 * j4]); ffma2(a2, v2.u2.y, wp[2 * j4 + 1]);
                    ffma2(a3, v3.u2.x, wp[2 * j4]); ffma2(a3, v3.u2.y, wp[2 * j4 + 1]);
                }
            } else {
                #pragma unroll
                for (int j4 = 0; j4 < 12; j4++) {
                    U4 v0; v0.f4 = *(const float4*)&hs[0][52 + 4 * j4];
                    U4 v1; v1.f4 = *(const float4*)&hs[1][52 + 4 * j4];
                    U4 v2; v2.f4 = *(const float4*)&hs[2][52 + 4 * j4];
                    U4 v3; v3.f4 = *(const float4*)&hs[3][52 + 4 * j4];
                    ffma2(a0, v0.u2.x, wp[2 * j4]); ffma2(a0, v0.u2.y, wp[2 * j4 + 1]);
                    ffma2(a1, v1.u2.x, wp[2 * j4]); ffma2(a1, v1.u2.y, wp[2 * j4 + 1]);
                    ffma2(a2, v2.u2.x, wp[2 * j4]); ffma2(a2, v2.u2.y, wp[2 * j4 + 1]);
                    ffma2(a3, v3.u2.x, wp[2 * j4]); ffma2(a3, v3.u2.y, wp[2 * j4 + 1]);
                }
            }
            float* zpf = (float*)&zp2[0][0] + 2 * c + kh;
            zpf[0 * G4 * 2] = hsum(a0);
            zpf[1 * G4 * 2] = hsum(a1);
            zpf[2 * G4 * 2] = hsum(a2);
            zpf[3 * G4 * 2] = hsum(a3);
        }

        if (kh) {
            BAR_ARRIVE(1);
            if (act && t + 1 < T25) {
                const float* zr = zin + ((long long)(b0 + gr) * T25 + (t + 1)) * G4 + gu;
                const int nb = (t + 1) & 1;
                zsm[nb][0][c] = __ldg(zr);
                zsm[nb][1][c] = __ldg(zr + 100);
                zsm[nb][2][c] = __ldg(zr + 200);
                zsm[nb][3][c] = __ldg(zr + 300);
            }
            BAR_SYNCN(2);
        } else {
            BAR_SYNCN(1);
            if (act) {
                const int bf = t & 1;
                float2 p0 = zp2[gr][gu];
                float2 p1 = zp2[gr][gu + 100];
                float2 p2 = zp2[gr][gu + 200];
                float2 p3 = zp2[gr][gu + 300];
                float zi = zsm[bf][0][c] + p0.x + p0.y;
                float zj = zsm[bf][1][c] + p1.x + p1.y;
                float zf = zsm[bf][2][c] + p2.x + p2.y;
                float zo = zsm[bf][3][c] + p3.x + p3.y;
                cst = cst * sigm(zf + 1.0f) + sigm(zi) * mytanh(zj);
                float hn = mytanh(cst) * sigm(zo);
                hs[gr][gu] = hn;
            }
            BAR_SYNCN(2);
        }
    }

    __syncthreads();
    for (int idx = tid; idx < 4 * 128; idx += RT) {
        int r = idx / 128, j = idx % 128;
        float a = bfc1[j];
        #pragma unroll 4
        for (int k = 0; k < HID; k++)
            a += hs[r][k] * __ldg(wfc1 + k * 128 + j);
        fc1s[r][j] = a;
    }
    __syncthreads();
    if (tid < 8) {
        int r = tid / 2, cc = tid % 2;
        float a = bfc2[cc];
        #pragma unroll 8
        for (int k = 0; k < 128; k++)
            a += fc1s[r][k] * __ldg(wfc2 + k * 2 + cc);
        out[(b0 + r) * 2 + cc] = a;
    }
}

// ---------------------------------------------------------------------------
extern "C" void kernel_launch(void* const* d_in, const int* in_sizes, int n_in,
                              void* d_out, int out_size)
{
    const int*   feats = (const int*)  d_in[0];
    const float* emb   = (const float*)d_in[1];
    const float* k1    = (const float*)d_in[2];
    const float* b1    = (const float*)d_in[3];
    const float* k2    = (const float*)d_in[4];
    const float* b2    = (const float*)d_in[5];
    const float* wfc1  = (const float*)d_in[6];
    const float* bfc1  = (const float*)d_in[7];
    const float* wfc2  = (const float*)d_in[8];
    const float* bfc2  = (const float*)d_in[9];
    float* out = (float*)d_out;

    float* z2x = nullptr;
    cudaGetSymbolAddress((void**)&z2x, g_z2x);

    cudaFuncSetAttribute(abc_kernel,
                         cudaFuncAttributeMaxDynamicSharedMemorySize, K1_SMEM_BYTES);

    // Kernel 1: gather + inproj1 + rec1 + inproj2 -> g_z2x
    abc_kernel<<<128, RT, K1_SMEM_BYTES>>>(feats, emb, k1, b1, k2, b2, z2x);
    // Kernel 2: rec2 + FC head -> out
    rec2_kernel<<<128, RT>>>(z2x, k2 + HID * G4, wfc1, bfc1, wfc2, bfc2, out);
}